// round 1
// baseline (speedup 1.0000x reference)
#include <cuda_runtime.h>

#define N_NODES 100000
#define N_EDGES 1200000
#define D_IN 64
#define D_HID 64
#define D_OUT 34

// Scratch (device globals — no allocation allowed)
__device__ float g_dinv[N_NODES];              // degree, then deg^-1/2 in place
__device__ float g_norm[N_EDGES];              // per-edge norm
__device__ float g_xw[N_NODES * D_HID];        // x @ W1
__device__ float g_h[N_NODES * D_HID];         // aggregated + relu + softmax
__device__ float g_hw[N_NODES * D_OUT];        // h @ W2

// ---------------- degree / norm ----------------

__global__ void k_deg_init() {
    int i = blockIdx.x * blockDim.x + threadIdx.x;
    if (i < N_NODES) g_dinv[i] = 1.0f;  // self-loop contributes 1
}

__global__ void k_deg_count(const int* __restrict__ dst, int E) {
    int e = blockIdx.x * blockDim.x + threadIdx.x;
    if (e < E) atomicAdd(&g_dinv[dst[e]], 1.0f);
}

__global__ void k_dinv() {
    int i = blockIdx.x * blockDim.x + threadIdx.x;
    if (i < N_NODES) g_dinv[i] = rsqrtf(g_dinv[i]);  // deg >= 1 always
}

__global__ void k_norm(const int* __restrict__ src, const int* __restrict__ dst, int E) {
    int e = blockIdx.x * blockDim.x + threadIdx.x;
    if (e < E) g_norm[e] = g_dinv[src[e]] * g_dinv[dst[e]];
}

// ---------------- GEMM n x 64 x 64 ----------------
// 8 warps/block, warp per node. W1 in smem, x row in smem.
__global__ void k_gemm64(const float* __restrict__ X, const float* __restrict__ W,
                         float* __restrict__ out, int n) {
    __shared__ float sW[64 * 64];
    __shared__ float sx[8][64];
    int tid = threadIdx.x;
    for (int i = tid; i < 64 * 64; i += 256) sW[i] = W[i];
    int warp = tid >> 5, lane = tid & 31;
    int node = blockIdx.x * 8 + warp;
    __syncthreads();
    if (node < n) {
        sx[warp][lane]      = X[node * 64 + lane];
        sx[warp][lane + 32] = X[node * 64 + lane + 32];
        __syncwarp();
        float a0 = 0.f, a1 = 0.f;
#pragma unroll
        for (int k = 0; k < 64; k++) {
            float xv = sx[warp][k];
            a0 = fmaf(xv, sW[k * 64 + lane], a0);
            a1 = fmaf(xv, sW[k * 64 + lane + 32], a1);
        }
        out[node * 64 + lane]      = a0;
        out[node * 64 + lane + 32] = a1;
    }
}

// ---------------- GEMM n x 64 x 34 ----------------
__global__ void k_gemm34(const float* __restrict__ X, const float* __restrict__ W,
                         float* __restrict__ out, int n) {
    __shared__ float sW[64 * D_OUT];
    __shared__ float sx[8][64];
    int tid = threadIdx.x;
    for (int i = tid; i < 64 * D_OUT; i += 256) sW[i] = W[i];
    int warp = tid >> 5, lane = tid & 31;
    int node = blockIdx.x * 8 + warp;
    __syncthreads();
    if (node < n) {
        sx[warp][lane]      = X[node * 64 + lane];
        sx[warp][lane + 32] = X[node * 64 + lane + 32];
        __syncwarp();
        float a0 = 0.f, a1 = 0.f;
#pragma unroll
        for (int k = 0; k < 64; k++) {
            float xv = sx[warp][k];
            if (lane < D_OUT)      a0 = fmaf(xv, sW[k * D_OUT + lane], a0);
            if (lane + 32 < D_OUT) a1 = fmaf(xv, sW[k * D_OUT + lane + 32], a1);
        }
        if (lane < D_OUT)      out[node * D_OUT + lane] = a0;
        if (lane + 32 < D_OUT) out[node * D_OUT + lane + 32] = a1;
    }
}

// ---------------- init with bias ----------------

__global__ void k_init_bias64(float* __restrict__ out, const float* __restrict__ b, int n) {
    int i = blockIdx.x * blockDim.x + threadIdx.x;
    if (i < n * 64) out[i] = b[i & 63];
}

__global__ void k_init_bias34(float* __restrict__ out, const float* __restrict__ b, int n) {
    int i = blockIdx.x * blockDim.x + threadIdx.x;
    if (i < n * D_OUT) out[i] = b[i % D_OUT];
}

// ---------------- edge aggregation (warp per edge) ----------------

__global__ void k_agg64(const int* __restrict__ src, const int* __restrict__ dst,
                        const float* __restrict__ feat, float* __restrict__ out, int E) {
    int t = blockIdx.x * blockDim.x + threadIdx.x;
    int e = t >> 5;
    int lane = t & 31;
    if (e < E) {
        int s = src[e], d = dst[e];
        float w = g_norm[e];
        atomicAdd(&out[d * 64 + lane],      w * feat[s * 64 + lane]);
        atomicAdd(&out[d * 64 + lane + 32], w * feat[s * 64 + lane + 32]);
    }
}

__global__ void k_agg34(const int* __restrict__ src, const int* __restrict__ dst,
                        const float* __restrict__ feat, float* __restrict__ out, int E) {
    int t = blockIdx.x * blockDim.x + threadIdx.x;
    int e = t >> 5;
    int lane = t & 31;
    if (e < E) {
        int s = src[e], d = dst[e];
        float w = g_norm[e];
        atomicAdd(&out[d * D_OUT + lane], w * feat[s * D_OUT + lane]);
        if (lane + 32 < D_OUT)
            atomicAdd(&out[d * D_OUT + lane + 32], w * feat[s * D_OUT + lane + 32]);
    }
}

// self-loop: out[i] += dinv[i]^2 * feat[i]  (plain add, separate launch)
__global__ void k_self64(const float* __restrict__ feat, float* __restrict__ out, int n) {
    int i = blockIdx.x * blockDim.x + threadIdx.x;
    if (i < n * 64) {
        int node = i >> 6;
        float w = g_dinv[node];
        out[i] += w * w * feat[i];
    }
}

__global__ void k_self34(const float* __restrict__ feat, float* __restrict__ out, int n) {
    int i = blockIdx.x * blockDim.x + threadIdx.x;
    if (i < n * D_OUT) {
        int node = i / D_OUT;
        float w = g_dinv[node];
        out[i] += w * w * feat[i];
    }
}

// ---------------- relu + softmax over dim=1 (warp per node) ----------------

__global__ void k_relu_softmax(float* __restrict__ h, int n) {
    int t = blockIdx.x * blockDim.x + threadIdx.x;
    int node = t >> 5;
    int lane = t & 31;
    if (node < n) {
        float v0 = fmaxf(h[node * 64 + lane], 0.0f);
        float v1 = fmaxf(h[node * 64 + lane + 32], 0.0f);
        float m = fmaxf(v0, v1);
#pragma unroll
        for (int off = 16; off > 0; off >>= 1)
            m = fmaxf(m, __shfl_xor_sync(0xFFFFFFFFu, m, off));
        float e0 = __expf(v0 - m);
        float e1 = __expf(v1 - m);
        float s = e0 + e1;
#pragma unroll
        for (int off = 16; off > 0; off >>= 1)
            s += __shfl_xor_sync(0xFFFFFFFFu, s, off);
        float inv = 1.0f / s;
        h[node * 64 + lane]      = e0 * inv;
        h[node * 64 + lane + 32] = e1 * inv;
    }
}

// ---------------- launch ----------------

extern "C" void kernel_launch(void* const* d_in, const int* in_sizes, int n_in,
                              void* d_out, int out_size) {
    const float* x   = (const float*)d_in[0];
    const int* eidx  = (const int*)d_in[1];
    const float* W1  = (const float*)d_in[2];
    const float* b1  = (const float*)d_in[3];
    const float* W2  = (const float*)d_in[4];
    const float* b2  = (const float*)d_in[5];
    float* out = (float*)d_out;

    int n = in_sizes[0] / D_IN;       // 100000
    int E = in_sizes[1] / 2;          // 1200000
    const int* src = eidx;
    const int* dst = eidx + E;

    float* dinv_base;
    cudaGetSymbolAddress((void**)&dinv_base, g_dinv);  // not needed for launch; kernels use symbol
    (void)dinv_base;

    float* xw; cudaGetSymbolAddress((void**)&xw, g_xw);
    float* h;  cudaGetSymbolAddress((void**)&h,  g_h);
    float* hw; cudaGetSymbolAddress((void**)&hw, g_hw);

    int T = 256;

    // degree + norm
    k_deg_init<<<(n + T - 1) / T, T>>>();
    k_deg_count<<<(E + T - 1) / T, T>>>(dst, E);
    k_dinv<<<(n + T - 1) / T, T>>>();
    k_norm<<<(E + T - 1) / T, T>>>(src, dst, E);

    // layer 1
    k_gemm64<<<(n + 7) / 8, 256>>>(x, W1, xw, n);
    k_init_bias64<<<(n * 64 + T - 1) / T, T>>>(h, b1, n);
    {
        long long threads = (long long)E * 32;
        k_agg64<<<(int)((threads + T - 1) / T), T>>>(src, dst, xw, h, E);
    }
    k_self64<<<(n * 64 + T - 1) / T, T>>>(xw, h, n);
    k_relu_softmax<<<(n * 32 + T - 1) / T, T>>>(h, n);

    // layer 2
    k_gemm34<<<(n + 7) / 8, 256>>>(h, W2, hw, n);
    k_init_bias34<<<(n * D_OUT + T - 1) / T, T>>>(out, b2, n);
    {
        long long threads = (long long)E * 32;
        k_agg34<<<(int)((threads + T - 1) / T), T>>>(src, dst, hw, out, E);
    }
    k_self34<<<(n * D_OUT + T - 1) / T, T>>>(hw, out, n);
}

// round 2
// speedup vs baseline: 1.8745x; 1.8745x over previous
#include <cuda_runtime.h>

#define N_NODES 100000
#define N_EDGES 1200000
#define D_IN 64
#define D_HID 64
#define D_OUT 34
#define FULL 0xFFFFFFFFu

// ---------------- scratch (device globals, no allocation) ----------------
__device__ int   g_deg[N_NODES];            // in-degree (edges only)
__device__ int   g_partial[1024];           // per-block sums for scan
__device__ int   g_rowstart[N_NODES + 1];   // CSR offsets
__device__ int   g_cursor[N_NODES];         // scatter cursors
__device__ int   g_csrc[N_EDGES];           // src ids grouped by dst
__device__ float g_dinv[N_NODES];           // deg^{-1/2} (incl self-loop)
__device__ float g_xw[N_NODES * D_HID];     // dinv .* (x @ W1)
__device__ float g_h[N_NODES * D_HID];      // softmax(relu(agg1))
__device__ float g_hw[N_NODES * D_OUT];     // dinv .* (h @ W2)

// ---------------- CSR build ----------------

__global__ void k_zero_deg() {
    int i = blockIdx.x * blockDim.x + threadIdx.x;
    if (i < N_NODES) g_deg[i] = 0;
}

__global__ void k_hist(const int* __restrict__ dst, int E) {
    int e = blockIdx.x * blockDim.x + threadIdx.x;
    if (e < E) atomicAdd(&g_deg[dst[e]], 1);
}

// per-block sums of g_deg
__global__ void k_blocksum(int n) {
    __shared__ int s[256];
    int t = threadIdx.x;
    int i = blockIdx.x * 256 + t;
    s[t] = (i < n) ? g_deg[i] : 0;
    __syncthreads();
    for (int off = 128; off > 0; off >>= 1) {
        if (t < off) s[t] += s[t + off];
        __syncthreads();
    }
    if (t == 0) g_partial[blockIdx.x] = s[0];
}

// exclusive scan of partials (single block, NB <= 512)
__global__ void k_scan_partials(int NB) {
    __shared__ int s[512];
    int t = threadIdx.x;
    int v = (t < NB) ? g_partial[t] : 0;
    s[t] = v;
    __syncthreads();
    for (int off = 1; off < 512; off <<= 1) {
        int x = 0;
        if (t >= off) x = s[t - off];
        __syncthreads();
        if (t >= off) s[t] += x;
        __syncthreads();
    }
    if (t < NB) g_partial[t] = s[t] - v;  // exclusive
}

// per-block exclusive scan + offset; also init cursor + dinv
__global__ void k_scan_block(int n, int E) {
    __shared__ int s[256];
    int t = threadIdx.x;
    int i = blockIdx.x * 256 + t;
    int v = (i < n) ? g_deg[i] : 0;
    s[t] = v;
    __syncthreads();
    for (int off = 1; off < 256; off <<= 1) {
        int x = 0;
        if (t >= off) x = s[t - off];
        __syncthreads();
        if (t >= off) s[t] += x;
        __syncthreads();
    }
    int base = g_partial[blockIdx.x];
    if (i < n) {
        int excl = base + s[t] - v;
        g_rowstart[i] = excl;
        g_cursor[i] = excl;
        g_dinv[i] = rsqrtf((float)(v + 1));  // +1 self-loop
        if (i == n - 1) g_rowstart[n] = E;
    }
}

__global__ void k_scatter(const int* __restrict__ src, const int* __restrict__ dst, int E) {
    int e = blockIdx.x * blockDim.x + threadIdx.x;
    if (e < E) {
        int pos = atomicAdd(&g_cursor[dst[e]], 1);
        g_csrc[pos] = src[e];
    }
}

// ---------------- GEMM n x 64 x 64, epilogue: scale row by dinv ----------------
// 8 warps/block, warp per node; lane handles cols (2*lane, 2*lane+1).
__global__ void k_gemm64(const float* __restrict__ X, const float* __restrict__ W,
                         float* __restrict__ out, int n) {
    __shared__ float sW[64 * 64];
    __shared__ float sx[8][64];
    int tid = threadIdx.x;
    for (int i = tid; i < 64 * 64; i += 256) sW[i] = W[i];
    int warp = tid >> 5, lane = tid & 31;
    int node = blockIdx.x * 8 + warp;
    __syncthreads();
    if (node < n) {
        sx[warp][lane]      = X[node * 64 + lane];
        sx[warp][lane + 32] = X[node * 64 + lane + 32];
        __syncwarp();
        float a0 = 0.f, a1 = 0.f;
#pragma unroll
        for (int k = 0; k < 64; k++) {
            float xv = sx[warp][k];
            float2 w = *(const float2*)&sW[k * 64 + 2 * lane];
            a0 = fmaf(xv, w.x, a0);
            a1 = fmaf(xv, w.y, a1);
        }
        float d = g_dinv[node];
        float2 r = {d * a0, d * a1};
        *(float2*)&out[node * 64 + 2 * lane] = r;
    }
}

// ---------------- GEMM n x 64 x 34, epilogue: scale row by dinv ----------------
__global__ void k_gemm34(const float* __restrict__ X, const float* __restrict__ W,
                         float* __restrict__ out, int n) {
    __shared__ float sW[64 * D_OUT];
    __shared__ float sx[8][64];
    int tid = threadIdx.x;
    for (int i = tid; i < 64 * D_OUT; i += 256) sW[i] = W[i];
    int warp = tid >> 5, lane = tid & 31;
    int node = blockIdx.x * 8 + warp;
    __syncthreads();
    if (node < n) {
        sx[warp][lane]      = X[node * 64 + lane];
        sx[warp][lane + 32] = X[node * 64 + lane + 32];
        __syncwarp();
        float a0 = 0.f, a1 = 0.f;
#pragma unroll
        for (int k = 0; k < 64; k++) {
            float xv = sx[warp][k];
            if (lane < D_OUT)      a0 = fmaf(xv, sW[k * D_OUT + lane], a0);
            if (lane + 32 < D_OUT) a1 = fmaf(xv, sW[k * D_OUT + lane + 32], a1);
        }
        float d = g_dinv[node];
        if (lane < D_OUT)      out[node * D_OUT + lane]      = d * a0;
        if (lane + 32 < D_OUT) out[node * D_OUT + lane + 32] = d * a1;
    }
}

// ---------------- fused agg1: gather-sum + self + bias + relu + softmax ----------
// warp per node; lane owns cols (2*lane, 2*lane+1)
__global__ void k_agg1(const float* __restrict__ feat, float* __restrict__ hout,
                       const float* __restrict__ b1, int n) {
    int t = blockIdx.x * blockDim.x + threadIdx.x;
    int node = t >> 5;
    int lane = t & 31;
    if (node >= n) return;

    float2 acc = *(const float2*)&feat[node * 64 + 2 * lane];  // self term
    int row = g_rowstart[node];
    int end = g_rowstart[node + 1];
    int cnt = end - row;

    for (int base = 0; base < cnt; base += 32) {
        int m = cnt - base; if (m > 32) m = 32;
        int sidx = 0;
        if (base + lane < cnt) sidx = g_csrc[row + base + lane];
        int j = 0;
        for (; j + 4 <= m; j += 4) {
            int s0 = __shfl_sync(FULL, sidx, j);
            int s1 = __shfl_sync(FULL, sidx, j + 1);
            int s2 = __shfl_sync(FULL, sidx, j + 2);
            int s3 = __shfl_sync(FULL, sidx, j + 3);
            float2 v0 = *(const float2*)&feat[s0 * 64 + 2 * lane];
            float2 v1 = *(const float2*)&feat[s1 * 64 + 2 * lane];
            float2 v2 = *(const float2*)&feat[s2 * 64 + 2 * lane];
            float2 v3 = *(const float2*)&feat[s3 * 64 + 2 * lane];
            acc.x += (v0.x + v1.x) + (v2.x + v3.x);
            acc.y += (v0.y + v1.y) + (v2.y + v3.y);
        }
        for (; j < m; j++) {
            int s0 = __shfl_sync(FULL, sidx, j);
            float2 v0 = *(const float2*)&feat[s0 * 64 + 2 * lane];
            acc.x += v0.x;
            acc.y += v0.y;
        }
    }

    float d = g_dinv[node];
    float v0 = fmaxf(fmaf(d, acc.x, b1[2 * lane]), 0.0f);
    float v1 = fmaxf(fmaf(d, acc.y, b1[2 * lane + 1]), 0.0f);
    float mx = fmaxf(v0, v1);
#pragma unroll
    for (int off = 16; off > 0; off >>= 1)
        mx = fmaxf(mx, __shfl_xor_sync(FULL, mx, off));
    float e0 = __expf(v0 - mx);
    float e1 = __expf(v1 - mx);
    float s = e0 + e1;
#pragma unroll
    for (int off = 16; off > 0; off >>= 1)
        s += __shfl_xor_sync(FULL, s, off);
    float inv = 1.0f / s;
    float2 r = {e0 * inv, e1 * inv};
    *(float2*)&hout[node * 64 + 2 * lane] = r;
}

// ---------------- fused agg2: gather-sum + self + bias -> out ----------------
// warp per node; lanes 0..16 own float2 cols (2*lane, 2*lane+1), lane16 covers 32,33
__global__ void k_agg2(const float* __restrict__ feat, float* __restrict__ out,
                       const float* __restrict__ b2, int n) {
    int t = blockIdx.x * blockDim.x + threadIdx.x;
    int node = t >> 5;
    int lane = t & 31;
    if (node >= n) return;

    bool act = (lane < 17);
    float2 acc = {0.f, 0.f};
    if (act) acc = *(const float2*)&feat[node * D_OUT + 2 * lane];  // self term

    int row = g_rowstart[node];
    int end = g_rowstart[node + 1];
    int cnt = end - row;

    for (int base = 0; base < cnt; base += 32) {
        int m = cnt - base; if (m > 32) m = 32;
        int sidx = 0;
        if (base + lane < cnt) sidx = g_csrc[row + base + lane];
        int j = 0;
        for (; j + 4 <= m; j += 4) {
            int s0 = __shfl_sync(FULL, sidx, j);
            int s1 = __shfl_sync(FULL, sidx, j + 1);
            int s2 = __shfl_sync(FULL, sidx, j + 2);
            int s3 = __shfl_sync(FULL, sidx, j + 3);
            if (act) {
                float2 v0 = *(const float2*)&feat[s0 * D_OUT + 2 * lane];
                float2 v1 = *(const float2*)&feat[s1 * D_OUT + 2 * lane];
                float2 v2 = *(const float2*)&feat[s2 * D_OUT + 2 * lane];
                float2 v3 = *(const float2*)&feat[s3 * D_OUT + 2 * lane];
                acc.x += (v0.x + v1.x) + (v2.x + v3.x);
                acc.y += (v0.y + v1.y) + (v2.y + v3.y);
            }
        }
        for (; j < m; j++) {
            int s0 = __shfl_sync(FULL, sidx, j);
            if (act) {
                float2 v0 = *(const float2*)&feat[s0 * D_OUT + 2 * lane];
                acc.x += v0.x;
                acc.y += v0.y;
            }
        }
    }

    if (act) {
        float d = g_dinv[node];
        float2 r = {fmaf(d, acc.x, b2[2 * lane]), fmaf(d, acc.y, b2[2 * lane + 1])};
        *(float2*)&out[node * D_OUT + 2 * lane] = r;
    }
}

// ---------------- launch ----------------

extern "C" void kernel_launch(void* const* d_in, const int* in_sizes, int n_in,
                              void* d_out, int out_size) {
    const float* x  = (const float*)d_in[0];
    const int* eidx = (const int*)d_in[1];
    const float* W1 = (const float*)d_in[2];
    const float* b1 = (const float*)d_in[3];
    const float* W2 = (const float*)d_in[4];
    const float* b2 = (const float*)d_in[5];
    float* out = (float*)d_out;

    int n = in_sizes[0] / D_IN;   // 100000
    int E = in_sizes[1] / 2;      // 1200000
    const int* src = eidx;
    const int* dst = eidx + E;

    float* xw; cudaGetSymbolAddress((void**)&xw, g_xw);
    float* h;  cudaGetSymbolAddress((void**)&h,  g_h);
    float* hw; cudaGetSymbolAddress((void**)&hw, g_hw);

    const int T = 256;
    int NB = (n + T - 1) / T;           // 391 blocks over nodes
    int EB = (E + T - 1) / T;           // edge blocks
    int WB = (n * 32 + T - 1) / T;      // warp-per-node blocks
    int GB = (n + 7) / 8;               // gemm blocks

    // CSR build + dinv
    k_zero_deg<<<NB, T>>>();
    k_hist<<<EB, T>>>(dst, E);
    k_blocksum<<<NB, T>>>(n);
    k_scan_partials<<<1, 512>>>(NB);
    k_scan_block<<<NB, T>>>(n, E);
    k_scatter<<<EB, T>>>(src, dst, E);

    // layer 1 (GEMM pre-scaled by dinv; agg fuses self+bias+relu+softmax)
    k_gemm64<<<GB, 256>>>(x, W1, xw, n);
    k_agg1<<<WB, T>>>(xw, h, b1, n);

    // layer 2
    k_gemm34<<<GB, 256>>>(h, W2, hw, n);
    k_agg2<<<WB, T>>>(hw, out, b2, n);
}

// round 4
// speedup vs baseline: 2.7495x; 1.4668x over previous
#include <cuda_runtime.h>

#define N_NODES 100000
#define N_EDGES 1200000
#define D_IN 64
#define D_HID 64
#define D_OUT 34
#define D_OUT_PAD 40
#define FULL 0xFFFFFFFFu

// ---------------- scratch (device globals, no allocation) ----------------
__device__ int      g_deg[N_NODES];
__device__ unsigned g_state[1024];              // lookback scan states
__device__ int      g_rowstart[N_NODES + 1];
__device__ int      g_cursor[N_NODES];
__device__ int      g_csrc[N_EDGES];
__device__ float    g_dinv[N_NODES];
__device__ float    g_xw[N_NODES * D_HID];      // dinv .* (x @ W1)
__device__ float    g_h[N_NODES * D_HID];       // softmax(relu(agg1))
__device__ float    g_hw[N_NODES * D_OUT_PAD];  // dinv .* (h @ W2), padded

// ---------------- CSR build ----------------

__global__ void k_hist(const int* __restrict__ dst, int E) {
    int e = blockIdx.x * blockDim.x + threadIdx.x;
    if (e < E) atomicAdd(&g_deg[dst[e]], 1);
}

// single-pass scan with decoupled lookback; also writes rowstart/cursor/dinv
#define ST_A (1u << 30)
#define ST_P (2u << 30)
#define VMASK ((1u << 30) - 1)

__global__ void k_scan(int n, int E) {
    __shared__ int s[256];
    __shared__ int sprefix;
    volatile unsigned* state = g_state;
    int b = blockIdx.x, t = threadIdx.x;
    int i = b * 256 + t;
    int v = (i < n) ? g_deg[i] : 0;
    s[t] = v;
    __syncthreads();
    for (int off = 1; off < 256; off <<= 1) {
        int x = 0;
        if (t >= off) x = s[t - off];
        __syncthreads();
        if (t >= off) s[t] += x;
        __syncthreads();
    }
    int incl = s[t];
    int total = s[255];

    if (b == 0) {
        if (t == 0) { state[0] = ST_P | (unsigned)total; sprefix = 0; }
    } else {
        if (t == 0) state[b] = ST_A | (unsigned)total;  // publish aggregate early
        if (t < 32) {
            int prefix = 0;
            int idx = b - 1;
            while (true) {
                int look = idx - t;
                unsigned st = ST_P;  // value 0 for out-of-range
                if (look >= 0) {
                    do { st = state[look]; } while ((st >> 30) == 0u);
                }
                unsigned pm = __ballot_sync(FULL, (st >> 30) == 2u);
                if (pm) {
                    int lp = __ffs(pm) - 1;  // nearest predecessor with full prefix
                    unsigned c = (t <= lp) ? (st & VMASK) : 0u;
#pragma unroll
                    for (int off = 16; off > 0; off >>= 1)
                        c += __shfl_xor_sync(FULL, c, off);
                    prefix += (int)c;
                    break;
                } else {
                    unsigned c = st & VMASK;
#pragma unroll
                    for (int off = 16; off > 0; off >>= 1)
                        c += __shfl_xor_sync(FULL, c, off);
                    prefix += (int)c;
                    idx -= 32;
                }
            }
            if (t == 0) {
                state[b] = ST_P | (unsigned)(prefix + total);
                sprefix = prefix;
            }
        }
    }
    __syncthreads();
    if (i < n) {
        int excl = sprefix + incl - v;
        g_rowstart[i] = excl;
        g_cursor[i] = excl;
        g_dinv[i] = rsqrtf((float)(v + 1));
        if (i == n - 1) g_rowstart[n] = E;
    }
}

__global__ void k_scatter(const int* __restrict__ src, const int* __restrict__ dst, int E) {
    int e = blockIdx.x * blockDim.x + threadIdx.x;
    if (e < E) {
        int pos = atomicAdd(&g_cursor[dst[e]], 1);
        g_csrc[pos] = src[e];
    }
}

// ---------------- register-tiled GEMM: n x 64 x 64, epilogue scale by dinv ----
// block 256 threads, tile 64 nodes x 64 cols, 4x4 outputs/thread, k-chunks of 16
__global__ void k_gemm64(const float* __restrict__ X, const float* __restrict__ W,
                         float* __restrict__ out, int n) {
    __shared__ float sX[64][20];   // [node][k], stride 20 (16B-aligned rows)
    __shared__ float sW[16][64];   // [k][col]
    int t = threadIdx.x;
    int tx = t & 15;          // col group: cols 4*tx..4*tx+3
    int ty = t >> 4;          // node group: nodes 4*ty..4*ty+3
    int nbase = blockIdx.x * 64;

    float acc[4][4];
#pragma unroll
    for (int i = 0; i < 4; i++)
#pragma unroll
        for (int j = 0; j < 4; j++) acc[i][j] = 0.f;

    int ldn = t >> 2, ldq = t & 3;              // X loader: node, k-quad
    int wk = t >> 4, wc = (t & 15) << 2;        // W loader: k row, col

    for (int k0 = 0; k0 < 64; k0 += 16) {
        int gnode = nbase + ldn; if (gnode >= n) gnode = n - 1;
        float4 xv = *(const float4*)&X[gnode * 64 + k0 + 4 * ldq];
        *(float4*)&sX[ldn][4 * ldq] = xv;
        float4 wv = *(const float4*)&W[(k0 + wk) * 64 + wc];
        *(float4*)&sW[wk][wc] = wv;
        __syncthreads();
#pragma unroll
        for (int k = 0; k < 16; k++) {
            float4 b = *(const float4*)&sW[k][4 * tx];
            float a0 = sX[4 * ty + 0][k];
            float a1 = sX[4 * ty + 1][k];
            float a2 = sX[4 * ty + 2][k];
            float a3 = sX[4 * ty + 3][k];
            acc[0][0] = fmaf(a0, b.x, acc[0][0]); acc[0][1] = fmaf(a0, b.y, acc[0][1]);
            acc[0][2] = fmaf(a0, b.z, acc[0][2]); acc[0][3] = fmaf(a0, b.w, acc[0][3]);
            acc[1][0] = fmaf(a1, b.x, acc[1][0]); acc[1][1] = fmaf(a1, b.y, acc[1][1]);
            acc[1][2] = fmaf(a1, b.z, acc[1][2]); acc[1][3] = fmaf(a1, b.w, acc[1][3]);
            acc[2][0] = fmaf(a2, b.x, acc[2][0]); acc[2][1] = fmaf(a2, b.y, acc[2][1]);
            acc[2][2] = fmaf(a2, b.z, acc[2][2]); acc[2][3] = fmaf(a2, b.w, acc[2][3]);
            acc[3][0] = fmaf(a3, b.x, acc[3][0]); acc[3][1] = fmaf(a3, b.y, acc[3][1]);
            acc[3][2] = fmaf(a3, b.z, acc[3][2]); acc[3][3] = fmaf(a3, b.w, acc[3][3]);
        }
        __syncthreads();
    }
#pragma unroll
    for (int i = 0; i < 4; i++) {
        int node = nbase + 4 * ty + i;
        if (node < n) {
            float d = g_dinv[node];
            float4 r = {d * acc[i][0], d * acc[i][1], d * acc[i][2], d * acc[i][3]};
            *(float4*)&out[node * 64 + 4 * tx] = r;
        }
    }
}

// ---------------- register-tiled GEMM: n x 64 x 34 -> padded 40 cols ---------
// block 160 threads (ty 0..15 x tx 0..9), tile 64 nodes x 40 cols
__global__ void k_gemm34(const float* __restrict__ X, const float* __restrict__ W,
                         float* __restrict__ out, int n) {
    __shared__ float sX[64][20];
    __shared__ float sW[16][40];
    int t = threadIdx.x;
    int tx = t % 10;
    int ty = t / 10;
    int nbase = blockIdx.x * 64;

    float acc[4][4];
#pragma unroll
    for (int i = 0; i < 4; i++)
#pragma unroll
        for (int j = 0; j < 4; j++) acc[i][j] = 0.f;

    for (int k0 = 0; k0 < 64; k0 += 16) {
        for (int i = t; i < 256; i += 160) {          // 64 nodes x 4 k-quads
            int node = i >> 2, q = i & 3;
            int gnode = nbase + node; if (gnode >= n) gnode = n - 1;
            float4 xv = *(const float4*)&X[gnode * 64 + k0 + 4 * q];
            *(float4*)&sX[node][4 * q] = xv;
        }
        for (int i = t; i < 640; i += 160) {          // 16 k x 40 cols
            int k = i / 40, c = i % 40;
            sW[k][c] = (c < D_OUT) ? W[(k0 + k) * D_OUT + c] : 0.f;
        }
        __syncthreads();
#pragma unroll
        for (int k = 0; k < 16; k++) {
            float4 b = *(const float4*)&sW[k][4 * tx];
            float a0 = sX[4 * ty + 0][k];
            float a1 = sX[4 * ty + 1][k];
            float a2 = sX[4 * ty + 2][k];
            float a3 = sX[4 * ty + 3][k];
            acc[0][0] = fmaf(a0, b.x, acc[0][0]); acc[0][1] = fmaf(a0, b.y, acc[0][1]);
            acc[0][2] = fmaf(a0, b.z, acc[0][2]); acc[0][3] = fmaf(a0, b.w, acc[0][3]);
            acc[1][0] = fmaf(a1, b.x, acc[1][0]); acc[1][1] = fmaf(a1, b.y, acc[1][1]);
            acc[1][2] = fmaf(a1, b.z, acc[1][2]); acc[1][3] = fmaf(a1, b.w, acc[1][3]);
            acc[2][0] = fmaf(a2, b.x, acc[2][0]); acc[2][1] = fmaf(a2, b.y, acc[2][1]);
            acc[2][2] = fmaf(a2, b.z, acc[2][2]); acc[2][3] = fmaf(a2, b.w, acc[2][3]);
            acc[3][0] = fmaf(a3, b.x, acc[3][0]); acc[3][1] = fmaf(a3, b.y, acc[3][1]);
            acc[3][2] = fmaf(a3, b.z, acc[3][2]); acc[3][3] = fmaf(a3, b.w, acc[3][3]);
        }
        __syncthreads();
    }
#pragma unroll
    for (int i = 0; i < 4; i++) {
        int node = nbase + 4 * ty + i;
        if (node < n) {
            float d = g_dinv[node];
            float4 r = {d * acc[i][0], d * acc[i][1], d * acc[i][2], d * acc[i][3]};
            *(float4*)&out[node * D_OUT_PAD + 4 * tx] = r;
        }
    }
}

// ---------------- agg1: warp/node, 2 rows per iter (half-warps), float4 ------
// fuses self + bias + relu + softmax
__global__ void k_agg1(const float* __restrict__ feat, float* __restrict__ hout,
                       const float* __restrict__ b1, int n) {
    int t = blockIdx.x * blockDim.x + threadIdx.x;
    int node = t >> 5;
    int lane = t & 31;
    if (node >= n) return;
    int half = lane >> 4;
    int hl = lane & 15;

    float4 acc = {0.f, 0.f, 0.f, 0.f};
    if (half == 0) acc = *(const float4*)&feat[node * 64 + 4 * hl];  // self term

    int row = g_rowstart[node];
    int cnt = g_rowstart[node + 1] - row;

    for (int base = 0; base < cnt; base += 32) {
        int m = cnt - base; if (m > 32) m = 32;
        int sidx = 0;
        if (base + lane < cnt) sidx = g_csrc[row + base + lane];
        int j = 0;
        for (; j + 4 <= m; j += 4) {
            int ra = __shfl_sync(FULL, sidx, j + half);
            int rb = __shfl_sync(FULL, sidx, j + 2 + half);
            float4 va = *(const float4*)&feat[ra * 64 + 4 * hl];
            float4 vb = *(const float4*)&feat[rb * 64 + 4 * hl];
            acc.x += va.x + vb.x; acc.y += va.y + vb.y;
            acc.z += va.z + vb.z; acc.w += va.w + vb.w;
        }
        for (; j < m; j += 2) {
            int take = j + half;
            bool act = take < m;
            int r = __shfl_sync(FULL, sidx, act ? take : j);
            if (act) {
                float4 v = *(const float4*)&feat[r * 64 + 4 * hl];
                acc.x += v.x; acc.y += v.y; acc.z += v.z; acc.w += v.w;
            }
        }
    }
    // combine halves (both halves end with identical sums)
    acc.x += __shfl_xor_sync(FULL, acc.x, 16);
    acc.y += __shfl_xor_sync(FULL, acc.y, 16);
    acc.z += __shfl_xor_sync(FULL, acc.z, 16);
    acc.w += __shfl_xor_sync(FULL, acc.w, 16);

    float d = g_dinv[node];
    float4 bb = ((const float4*)b1)[hl];
    float v0 = fmaxf(fmaf(d, acc.x, bb.x), 0.f);
    float v1 = fmaxf(fmaf(d, acc.y, bb.y), 0.f);
    float v2 = fmaxf(fmaf(d, acc.z, bb.z), 0.f);
    float v3 = fmaxf(fmaf(d, acc.w, bb.w), 0.f);
    float mx = fmaxf(fmaxf(v0, v1), fmaxf(v2, v3));
#pragma unroll
    for (int off = 8; off > 0; off >>= 1)
        mx = fmaxf(mx, __shfl_xor_sync(FULL, mx, off));
    float e0 = __expf(v0 - mx), e1 = __expf(v1 - mx);
    float e2 = __expf(v2 - mx), e3 = __expf(v3 - mx);
    float s = (e0 + e1) + (e2 + e3);
#pragma unroll
    for (int off = 8; off > 0; off >>= 1)
        s += __shfl_xor_sync(FULL, s, off);
    float inv = 1.0f / s;
    if (half == 0) {
        float4 r = {e0 * inv, e1 * inv, e2 * inv, e3 * inv};
        *(float4*)&hout[node * 64 + 4 * hl] = r;
    }
}

// ---------------- agg2: warp/node over padded 40-col feat, write 34-col out --
__global__ void k_agg2(const float* __restrict__ feat, float* __restrict__ out,
                       const float* __restrict__ b2, int n) {
    int t = blockIdx.x * blockDim.x + threadIdx.x;
    int node = t >> 5;
    int lane = t & 31;
    if (node >= n) return;
    int half = lane >> 4;
    int hl = lane & 15;
    bool act = hl < 10;

    float4 acc = {0.f, 0.f, 0.f, 0.f};
    if (half == 0 && act) acc = *(const float4*)&feat[node * D_OUT_PAD + 4 * hl];

    int row = g_rowstart[node];
    int cnt = g_rowstart[node + 1] - row;

    for (int base = 0; base < cnt; base += 32) {
        int m = cnt - base; if (m > 32) m = 32;
        int sidx = 0;
        if (base + lane < cnt) sidx = g_csrc[row + base + lane];
        int j = 0;
        for (; j + 4 <= m; j += 4) {
            int ra = __shfl_sync(FULL, sidx, j + half);
            int rb = __shfl_sync(FULL, sidx, j + 2 + half);
            if (act) {
                float4 va = *(const float4*)&feat[ra * D_OUT_PAD + 4 * hl];
                float4 vb = *(const float4*)&feat[rb * D_OUT_PAD + 4 * hl];
                acc.x += va.x + vb.x; acc.y += va.y + vb.y;
                acc.z += va.z + vb.z; acc.w += va.w + vb.w;
            }
        }
        for (; j < m; j += 2) {
            int take = j + half;
            bool a2v = take < m;
            int r = __shfl_sync(FULL, sidx, a2v ? take : j);
            if (a2v && act) {
                float4 v = *(const float4*)&feat[r * D_OUT_PAD + 4 * hl];
                acc.x += v.x; acc.y += v.y; acc.z += v.z; acc.w += v.w;
            }
        }
    }
    acc.x += __shfl_xor_sync(FULL, acc.x, 16);
    acc.y += __shfl_xor_sync(FULL, acc.y, 16);
    acc.z += __shfl_xor_sync(FULL, acc.z, 16);
    acc.w += __shfl_xor_sync(FULL, acc.w, 16);

    if (half == 0) {
        float d = g_dinv[node];
        long long obase = (long long)node * D_OUT;
        if (hl < 8) {
            float4 bb = ((const float4*)b2)[hl];
            float2 r0 = {fmaf(d, acc.x, bb.x), fmaf(d, acc.y, bb.y)};
            float2 r1 = {fmaf(d, acc.z, bb.z), fmaf(d, acc.w, bb.w)};
            *(float2*)&out[obase + 4 * hl]     = r0;
            *(float2*)&out[obase + 4 * hl + 2] = r1;
        } else if (hl == 8) {
            float2 bb = *(const float2*)&b2[32];
            float2 r0 = {fmaf(d, acc.x, bb.x), fmaf(d, acc.y, bb.y)};
            *(float2*)&out[obase + 32] = r0;
        }
    }
}

// ---------------- launch ----------------

extern "C" void kernel_launch(void* const* d_in, const int* in_sizes, int n_in,
                              void* d_out, int out_size) {
    const float* x  = (const float*)d_in[0];
    const int* eidx = (const int*)d_in[1];
    const float* W1 = (const float*)d_in[2];
    const float* b1 = (const float*)d_in[3];
    const float* W2 = (const float*)d_in[4];
    const float* b2 = (const float*)d_in[5];
    float* out = (float*)d_out;

    int n = in_sizes[0] / D_IN;   // 100000
    int E = in_sizes[1] / 2;      // 1200000
    const int* src = eidx;
    const int* dst = eidx + E;

    float* xw; cudaGetSymbolAddress((void**)&xw, g_xw);
    float* h;  cudaGetSymbolAddress((void**)&h,  g_h);
    float* hw; cudaGetSymbolAddress((void**)&hw, g_hw);
    void* pdeg;   cudaGetSymbolAddress(&pdeg, g_deg);
    void* pstate; cudaGetSymbolAddress(&pstate, g_state);

    const int T = 256;
    int NB = (n + T - 1) / T;
    int EB = (E + T - 1) / T;
    int WB = (n * 32 + T - 1) / T;
    int GB = (n + 63) / 64;

    cudaMemsetAsync(pdeg, 0, n * sizeof(int));
    cudaMemsetAsync(pstate, 0, NB * sizeof(unsigned));

    k_hist<<<EB, T>>>(dst, E);
    k_scan<<<NB, T>>>(n, E);
    k_scatter<<<EB, T>>>(src, dst, E);

    k_gemm64<<<GB, 256>>>(x, W1, xw, n);
    k_agg1<<<WB, T>>>(xw, h, b1, n);

    k_gemm34<<<GB, 160>>>(h, W2, hw, n);
    k_agg2<<<WB, T>>>(hw, out, b2, n);
}

// round 6
// speedup vs baseline: 2.8436x; 1.0342x over previous
#include <cuda_runtime.h>

#define N_NODES 100000
#define N_EDGES 1200000
#define D_IN 64
#define D_HID 64
#define D_OUT 34
#define D_OUT_PAD 40
#define FULL 0xFFFFFFFFu

// ---------------- scratch (device globals, no allocation) ----------------
__device__ int      g_deg[N_NODES];
__device__ unsigned g_state[1024];
__device__ int      g_rowstart[N_NODES + 1];
__device__ int      g_cursor[N_NODES];
__device__ int      g_csrc[N_EDGES];
__device__ float    g_dinv[N_NODES];
__device__ float    g_xw[N_NODES * D_HID];      // x @ W1 (UNscaled)
__device__ float    g_h[N_NODES * D_HID];       // softmax(relu(agg1))
__device__ float    g_hw[N_NODES * D_OUT_PAD];  // dinv .* (h @ W2), padded

// ---------------- CSR build ----------------

__global__ void k_hist(const int* __restrict__ dst, int E) {
    int e = blockIdx.x * blockDim.x + threadIdx.x;
    if (e < E) atomicAdd(&g_deg[dst[e]], 1);
}

#define ST_A (1u << 30)
#define ST_P (2u << 30)
#define VMASK ((1u << 30) - 1)

__global__ void k_scan(int n, int E) {
    __shared__ int s[256];
    __shared__ int sprefix;
    volatile unsigned* state = g_state;
    int b = blockIdx.x, t = threadIdx.x;
    int i = b * 256 + t;
    int v = (i < n) ? g_deg[i] : 0;
    s[t] = v;
    __syncthreads();
    for (int off = 1; off < 256; off <<= 1) {
        int x = 0;
        if (t >= off) x = s[t - off];
        __syncthreads();
        if (t >= off) s[t] += x;
        __syncthreads();
    }
    int incl = s[t];
    int total = s[255];

    if (b == 0) {
        if (t == 0) { state[0] = ST_P | (unsigned)total; sprefix = 0; }
    } else {
        if (t == 0) state[b] = ST_A | (unsigned)total;
        if (t < 32) {
            int prefix = 0;
            int idx = b - 1;
            while (true) {
                int look = idx - t;
                unsigned st = ST_P;
                if (look >= 0) {
                    do { st = state[look]; } while ((st >> 30) == 0u);
                }
                unsigned pm = __ballot_sync(FULL, (st >> 30) == 2u);
                if (pm) {
                    int lp = __ffs(pm) - 1;
                    unsigned c = (t <= lp) ? (st & VMASK) : 0u;
#pragma unroll
                    for (int off = 16; off > 0; off >>= 1)
                        c += __shfl_xor_sync(FULL, c, off);
                    prefix += (int)c;
                    break;
                } else {
                    unsigned c = st & VMASK;
#pragma unroll
                    for (int off = 16; off > 0; off >>= 1)
                        c += __shfl_xor_sync(FULL, c, off);
                    prefix += (int)c;
                    idx -= 32;
                }
            }
            if (t == 0) {
                state[b] = ST_P | (unsigned)(prefix + total);
                sprefix = prefix;
            }
        }
    }
    __syncthreads();
    if (i < n) {
        int excl = sprefix + incl - v;
        g_rowstart[i] = excl;
        g_cursor[i] = excl;
        g_dinv[i] = rsqrtf((float)(v + 1));
        if (i == n - 1) g_rowstart[n] = E;
    }
}

__global__ void k_scatter(const int* __restrict__ src, const int* __restrict__ dst, int E) {
    int e = blockIdx.x * blockDim.x + threadIdx.x;
    if (e < E) {
        int pos = atomicAdd(&g_cursor[dst[e]], 1);
        g_csrc[pos] = src[e];
    }
}

// ---------------- GEMM v2: n x 64 x 64, tile 128 nodes x 64 cols -------------
// 256 threads, 8x4 acc/thread, A transposed in smem. No dinv (moved to agg1).
__global__ void k_gemm64(const float* __restrict__ X, const float* __restrict__ W,
                         float* __restrict__ out, int n) {
    __shared__ float sA[16][132];   // [k][node], stride 132 (16B aligned, conflict-free)
    __shared__ float sW[16][64];    // [k][col]
    int t = threadIdx.x;
    int tx = t & 15;                // col quad: cols 4*tx..4*tx+3
    int ty = t >> 4;                // node octet: nodes 8*ty..8*ty+7
    int nbase = blockIdx.x * 128;

    float acc[8][4];
#pragma unroll
    for (int i = 0; i < 8; i++)
#pragma unroll
        for (int j = 0; j < 4; j++) acc[i][j] = 0.f;

    int ldn = t & 127;              // A loader: node
    int ldq = (t >> 7) * 2;         // A loader: k-quad base (0 or 2)
    int wk = t >> 4, wc = (t & 15) << 2;  // W loader

    for (int k0 = 0; k0 < 64; k0 += 16) {
        int gnode = nbase + ldn; if (gnode >= n) gnode = n - 1;
        float4 a0 = *(const float4*)&X[gnode * 64 + k0 + 4 * ldq];
        float4 a1 = *(const float4*)&X[gnode * 64 + k0 + 4 * ldq + 4];
        sA[4 * ldq + 0][ldn] = a0.x; sA[4 * ldq + 1][ldn] = a0.y;
        sA[4 * ldq + 2][ldn] = a0.z; sA[4 * ldq + 3][ldn] = a0.w;
        sA[4 * ldq + 4][ldn] = a1.x; sA[4 * ldq + 5][ldn] = a1.y;
        sA[4 * ldq + 6][ldn] = a1.z; sA[4 * ldq + 7][ldn] = a1.w;
        float4 wv = *(const float4*)&W[(k0 + wk) * 64 + wc];
        *(float4*)&sW[wk][wc] = wv;
        __syncthreads();
#pragma unroll
        for (int k = 0; k < 16; k++) {
            float4 b  = *(const float4*)&sW[k][4 * tx];
            float4 aL = *(const float4*)&sA[k][8 * ty];
            float4 aH = *(const float4*)&sA[k][8 * ty + 4];
            acc[0][0] = fmaf(aL.x, b.x, acc[0][0]); acc[0][1] = fmaf(aL.x, b.y, acc[0][1]);
            acc[0][2] = fmaf(aL.x, b.z, acc[0][2]); acc[0][3] = fmaf(aL.x, b.w, acc[0][3]);
            acc[1][0] = fmaf(aL.y, b.x, acc[1][0]); acc[1][1] = fmaf(aL.y, b.y, acc[1][1]);
            acc[1][2] = fmaf(aL.y, b.z, acc[1][2]); acc[1][3] = fmaf(aL.y, b.w, acc[1][3]);
            acc[2][0] = fmaf(aL.z, b.x, acc[2][0]); acc[2][1] = fmaf(aL.z, b.y, acc[2][1]);
            acc[2][2] = fmaf(aL.z, b.z, acc[2][2]); acc[2][3] = fmaf(aL.z, b.w, acc[2][3]);
            acc[3][0] = fmaf(aL.w, b.x, acc[3][0]); acc[3][1] = fmaf(aL.w, b.y, acc[3][1]);
            acc[3][2] = fmaf(aL.w, b.z, acc[3][2]); acc[3][3] = fmaf(aL.w, b.w, acc[3][3]);
            acc[4][0] = fmaf(aH.x, b.x, acc[4][0]); acc[4][1] = fmaf(aH.x, b.y, acc[4][1]);
            acc[4][2] = fmaf(aH.x, b.z, acc[4][2]); acc[4][3] = fmaf(aH.x, b.w, acc[4][3]);
            acc[5][0] = fmaf(aH.y, b.x, acc[5][0]); acc[5][1] = fmaf(aH.y, b.y, acc[5][1]);
            acc[5][2] = fmaf(aH.y, b.z, acc[5][2]); acc[5][3] = fmaf(aH.y, b.w, acc[5][3]);
            acc[6][0] = fmaf(aH.z, b.x, acc[6][0]); acc[6][1] = fmaf(aH.z, b.y, acc[6][1]);
            acc[6][2] = fmaf(aH.z, b.z, acc[6][2]); acc[6][3] = fmaf(aH.z, b.w, acc[6][3]);
            acc[7][0] = fmaf(aH.w, b.x, acc[7][0]); acc[7][1] = fmaf(aH.w, b.y, acc[7][1]);
            acc[7][2] = fmaf(aH.w, b.z, acc[7][2]); acc[7][3] = fmaf(aH.w, b.w, acc[7][3]);
        }
        __syncthreads();
    }
#pragma unroll
    for (int i = 0; i < 8; i++) {
        int node = nbase + 8 * ty + i;
        if (node < n) {
            float4 r = {acc[i][0], acc[i][1], acc[i][2], acc[i][3]};
            *(float4*)&out[node * 64 + 4 * tx] = r;
        }
    }
}

// ---------------- GEMM: n x 64 x 34 -> padded 40 cols, prescale by dinv ------
__global__ void k_gemm34(const float* __restrict__ X, const float* __restrict__ W,
                         float* __restrict__ out, int n) {
    __shared__ float sX[64][20];
    __shared__ float sW[16][40];
    int t = threadIdx.x;
    int tx = t % 10;
    int ty = t / 10;
    int nbase = blockIdx.x * 64;

    float acc[4][4];
#pragma unroll
    for (int i = 0; i < 4; i++)
#pragma unroll
        for (int j = 0; j < 4; j++) acc[i][j] = 0.f;

    for (int k0 = 0; k0 < 64; k0 += 16) {
        for (int i = t; i < 256; i += 160) {
            int node = i >> 2, q = i & 3;
            int gnode = nbase + node; if (gnode >= n) gnode = n - 1;
            float4 xv = *(const float4*)&X[gnode * 64 + k0 + 4 * q];
            *(float4*)&sX[node][4 * q] = xv;
        }
        for (int i = t; i < 640; i += 160) {
            int k = i / 40, c = i % 40;
            sW[k][c] = (c < D_OUT) ? W[(k0 + k) * D_OUT + c] : 0.f;
        }
        __syncthreads();
#pragma unroll
        for (int k = 0; k < 16; k++) {
            float4 b = *(const float4*)&sW[k][4 * tx];
            float a0 = sX[4 * ty + 0][k];
            float a1 = sX[4 * ty + 1][k];
            float a2 = sX[4 * ty + 2][k];
            float a3 = sX[4 * ty + 3][k];
            acc[0][0] = fmaf(a0, b.x, acc[0][0]); acc[0][1] = fmaf(a0, b.y, acc[0][1]);
            acc[0][2] = fmaf(a0, b.z, acc[0][2]); acc[0][3] = fmaf(a0, b.w, acc[0][3]);
            acc[1][0] = fmaf(a1, b.x, acc[1][0]); acc[1][1] = fmaf(a1, b.y, acc[1][1]);
            acc[1][2] = fmaf(a1, b.z, acc[1][2]); acc[1][3] = fmaf(a1, b.w, acc[1][3]);
            acc[2][0] = fmaf(a2, b.x, acc[2][0]); acc[2][1] = fmaf(a2, b.y, acc[2][1]);
            acc[2][2] = fmaf(a2, b.z, acc[2][2]); acc[2][3] = fmaf(a2, b.w, acc[2][3]);
            acc[3][0] = fmaf(a3, b.x, acc[3][0]); acc[3][1] = fmaf(a3, b.y, acc[3][1]);
            acc[3][2] = fmaf(a3, b.z, acc[3][2]); acc[3][3] = fmaf(a3, b.w, acc[3][3]);
        }
        __syncthreads();
    }
#pragma unroll
    for (int i = 0; i < 4; i++) {
        int node = nbase + 4 * ty + i;
        if (node < n) {
            float d = g_dinv[node];
            float4 r = {d * acc[i][0], d * acc[i][1], d * acc[i][2], d * acc[i][3]};
            *(float4*)&out[node * D_OUT_PAD + 4 * tx] = r;
        }
    }
}

// ---------------- agg1: gather dinv[s]-weighted rows + self + bias + relu + softmax
// warp per node, 2 rows per iter via half-warps, float4 per lane
__global__ void k_agg1(const float* __restrict__ feat, float* __restrict__ hout,
                       const float* __restrict__ b1, int n) {
    int t = blockIdx.x * blockDim.x + threadIdx.x;
    int node = t >> 5;
    int lane = t & 31;
    if (node >= n) return;
    int half = lane >> 4;
    int hl = lane & 15;

    float d = g_dinv[node];
    float4 acc = {0.f, 0.f, 0.f, 0.f};
    if (half == 0) {
        float4 f = *(const float4*)&feat[node * 64 + 4 * hl];
        acc.x = d * f.x; acc.y = d * f.y; acc.z = d * f.z; acc.w = d * f.w;  // self (x dinv once; epilogue adds the second)
    }

    int row = g_rowstart[node];
    int cnt = g_rowstart[node + 1] - row;

    for (int base = 0; base < cnt; base += 32) {
        int m = cnt - base; if (m > 32) m = 32;
        int sidx = 0;
        if (base + lane < cnt) sidx = g_csrc[row + base + lane];
        int j = 0;
        for (; j + 4 <= m; j += 4) {
            int ra = __shfl_sync(FULL, sidx, j + half);
            int rb = __shfl_sync(FULL, sidx, j + 2 + half);
            float da = g_dinv[ra];
            float db = g_dinv[rb];
            float4 va = *(const float4*)&feat[ra * 64 + 4 * hl];
            float4 vb = *(const float4*)&feat[rb * 64 + 4 * hl];
            acc.x = fmaf(da, va.x, acc.x); acc.x = fmaf(db, vb.x, acc.x);
            acc.y = fmaf(da, va.y, acc.y); acc.y = fmaf(db, vb.y, acc.y);
            acc.z = fmaf(da, va.z, acc.z); acc.z = fmaf(db, vb.z, acc.z);
            acc.w = fmaf(da, va.w, acc.w); acc.w = fmaf(db, vb.w, acc.w);
        }
        for (; j < m; j += 2) {
            int take = j + half;
            bool act = take < m;
            int r = __shfl_sync(FULL, sidx, act ? take : j);
            if (act) {
                float dr = g_dinv[r];
                float4 v = *(const float4*)&feat[r * 64 + 4 * hl];
                acc.x = fmaf(dr, v.x, acc.x); acc.y = fmaf(dr, v.y, acc.y);
                acc.z = fmaf(dr, v.z, acc.z); acc.w = fmaf(dr, v.w, acc.w);
            }
        }
    }
    acc.x += __shfl_xor_sync(FULL, acc.x, 16);
    acc.y += __shfl_xor_sync(FULL, acc.y, 16);
    acc.z += __shfl_xor_sync(FULL, acc.z, 16);
    acc.w += __shfl_xor_sync(FULL, acc.w, 16);

    float4 bb = ((const float4*)b1)[hl];
    float v0 = fmaxf(fmaf(d, acc.x, bb.x), 0.f);
    float v1 = fmaxf(fmaf(d, acc.y, bb.y), 0.f);
    float v2 = fmaxf(fmaf(d, acc.z, bb.z), 0.f);
    float v3 = fmaxf(fmaf(d, acc.w, bb.w), 0.f);
    float mx = fmaxf(fmaxf(v0, v1), fmaxf(v2, v3));
#pragma unroll
    for (int off = 8; off > 0; off >>= 1)
        mx = fmaxf(mx, __shfl_xor_sync(FULL, mx, off));
    float e0 = __expf(v0 - mx), e1 = __expf(v1 - mx);
    float e2 = __expf(v2 - mx), e3 = __expf(v3 - mx);
    float s = (e0 + e1) + (e2 + e3);
#pragma unroll
    for (int off = 8; off > 0; off >>= 1)
        s += __shfl_xor_sync(FULL, s, off);
    float inv = 1.0f / s;
    if (half == 0) {
        float4 r = {e0 * inv, e1 * inv, e2 * inv, e3 * inv};
        *(float4*)&hout[node * 64 + 4 * hl] = r;
    }
}

// ---------------- agg2: padded 40-col gather, write 34-col out ---------------
__global__ void k_agg2(const float* __restrict__ feat, float* __restrict__ out,
                       const float* __restrict__ b2, int n) {
    int t = blockIdx.x * blockDim.x + threadIdx.x;
    int node = t >> 5;
    int lane = t & 31;
    if (node >= n) return;
    int half = lane >> 4;
    int hl = lane & 15;
    bool act = hl < 10;

    float4 acc = {0.f, 0.f, 0.f, 0.f};
    if (half == 0 && act) acc = *(const float4*)&feat[node * D_OUT_PAD + 4 * hl];

    int row = g_rowstart[node];
    int cnt = g_rowstart[node + 1] - row;

    for (int base = 0; base < cnt; base += 32) {
        int m = cnt - base; if (m > 32) m = 32;
        int sidx = 0;
        if (base + lane < cnt) sidx = g_csrc[row + base + lane];
        int j = 0;
        for (; j + 4 <= m; j += 4) {
            int ra = __shfl_sync(FULL, sidx, j + half);
            int rb = __shfl_sync(FULL, sidx, j + 2 + half);
            if (act) {
                float4 va = *(const float4*)&feat[ra * D_OUT_PAD + 4 * hl];
                float4 vb = *(const float4*)&feat[rb * D_OUT_PAD + 4 * hl];
                acc.x += va.x + vb.x; acc.y += va.y + vb.y;
                acc.z += va.z + vb.z; acc.w += va.w + vb.w;
            }
        }
        for (; j < m; j += 2) {
            int take = j + half;
            bool a2v = take < m;
            int r = __shfl_sync(FULL, sidx, a2v ? take : j);
            if (a2v && act) {
                float4 v = *(const float4*)&feat[r * D_OUT_PAD + 4 * hl];
                acc.x += v.x; acc.y += v.y; acc.z += v.z; acc.w += v.w;
            }
        }
    }
    acc.x += __shfl_xor_sync(FULL, acc.x, 16);
    acc.y += __shfl_xor_sync(FULL, acc.y, 16);
    acc.z += __shfl_xor_sync(FULL, acc.z, 16);
    acc.w += __shfl_xor_sync(FULL, acc.w, 16);

    if (half == 0) {
        float d = g_dinv[node];
        long long obase = (long long)node * D_OUT;
        if (hl < 8) {
            float4 bb = ((const float4*)b2)[hl];
            float2 r0 = {fmaf(d, acc.x, bb.x), fmaf(d, acc.y, bb.y)};
            float2 r1 = {fmaf(d, acc.z, bb.z), fmaf(d, acc.w, bb.w)};
            *(float2*)&out[obase + 4 * hl]     = r0;
            *(float2*)&out[obase + 4 * hl + 2] = r1;
        } else if (hl == 8) {
            float2 bb = *(const float2*)&b2[32];
            float2 r0 = {fmaf(d, acc.x, bb.x), fmaf(d, acc.y, bb.y)};
            *(float2*)&out[obase + 32] = r0;
        }
    }
}

// ---------------- launch ----------------

extern "C" void kernel_launch(void* const* d_in, const int* in_sizes, int n_in,
                              void* d_out, int out_size) {
    const float* x  = (const float*)d_in[0];
    const int* eidx = (const int*)d_in[1];
    const float* W1 = (const float*)d_in[2];
    const float* b1 = (const float*)d_in[3];
    const float* W2 = (const float*)d_in[4];
    const float* b2 = (const float*)d_in[5];
    float* out = (float*)d_out;

    int n = in_sizes[0] / D_IN;   // 100000
    int E = in_sizes[1] / 2;      // 1200000
    const int* src = eidx;
    const int* dst = eidx + E;

    float* xw; cudaGetSymbolAddress((void**)&xw, g_xw);
    float* h;  cudaGetSymbolAddress((void**)&h,  g_h);
    float* hw; cudaGetSymbolAddress((void**)&hw, g_hw);
    void* pdeg;   cudaGetSymbolAddress(&pdeg, g_deg);
    void* pstate; cudaGetSymbolAddress(&pstate, g_state);

    const int T = 256;
    int NB = (n + T - 1) / T;
    int EB = (E + T - 1) / T;
    int WB = (n * 32 + T - 1) / T;
    int GB64 = (n + 127) / 128;
    int GB34 = (n + 63) / 64;

    // one-time side-stream setup (host objects only; falls back to serial)
    static cudaStream_t s2 = 0;
    static cudaEvent_t evF = 0, evJ = 0;
    static int inited = 0;
    if (!inited) {
        if (cudaStreamCreateWithFlags(&s2, cudaStreamNonBlocking) != cudaSuccess) s2 = 0;
        if (s2) {
            if (cudaEventCreateWithFlags(&evF, cudaEventDisableTiming) != cudaSuccess ||
                cudaEventCreateWithFlags(&evJ, cudaEventDisableTiming) != cudaSuccess) {
                s2 = 0;
            }
        }
        inited = 1;
    }

    if (s2) {
        // fork: CSR build on side stream, gemm64 on main stream
        cudaEventRecord(evF, 0);
        cudaStreamWaitEvent(s2, evF, 0);
        cudaMemsetAsync(pdeg, 0, n * sizeof(int), s2);
        cudaMemsetAsync(pstate, 0, NB * sizeof(unsigned), s2);
        k_hist<<<EB, T, 0, s2>>>(dst, E);
        k_scan<<<NB, T, 0, s2>>>(n, E);
        k_scatter<<<EB, T, 0, s2>>>(src, dst, E);
        cudaEventRecord(evJ, s2);

        k_gemm64<<<GB64, 256>>>(x, W1, xw, n);

        cudaStreamWaitEvent(0, evJ, 0);
    } else {
        cudaMemsetAsync(pdeg, 0, n * sizeof(int));
        cudaMemsetAsync(pstate, 0, NB * sizeof(unsigned));
        k_hist<<<EB, T>>>(dst, E);
        k_scan<<<NB, T>>>(n, E);
        k_scatter<<<EB, T>>>(src, dst, E);
        k_gemm64<<<GB64, 256>>>(x, W1, xw, n);
    }

    k_agg1<<<WB, T>>>(xw, h, b1, n);
    k_gemm34<<<GB34, 160>>>(h, W2, hw, n);
    k_agg2<<<WB, T>>>(hw, out, b2, n);
}